// round 7
// baseline (speedup 1.0000x reference)
#include <cuda_runtime.h>
#include <math.h>

#define NNODES 8192
#define NEDGES 65536
#define NSURF  40000
#define NUNIQ  6000
#define NGRAPH 16
#define DIMF   1024
#define HID    64
#define EPSV   1e-5f
#define SLOPE  0.01f

// ---------------- scratch (device globals; referenced ONLY in device code) ----------------
__device__ float    g_feat[NNODES*DIMF];
__device__ float    g_acc [NNODES*DIMF];
__device__ unsigned g_agg [NNODES*DIMF];     // tf32 bits, A in FRAGMENT layout
__device__ unsigned g_bw  [4*DIMF*DIMF];     // tf32 bits, B in FRAGMENT layout (4 layers)
__device__ float    g_gemm[NNODES*DIMF];
__device__ float    g_surfy[NSURF*HID];
__device__ float    g_ressum[NNODES*HID];
__device__ float    g_rescnt[NNODES];
__device__ float    g_s[NUNIQ*HID];
__device__ float    g_su[NNODES];
__device__ int      g_csru[NEDGES];
__device__ int      g_rowptr[NNODES+1];
__device__ float    g_stats [2*HID];
__device__ float    g_stats2[2*HID];
__device__ float    g_nf[NNODES*HID];
__device__ float    g_y2[NUNIQ*HID];
__device__ float    g_nssum[NGRAPH*HID];
__device__ float    g_nscnt[NGRAPH];

// A fragment layout: A_perm[mt][kt][lane][reg], mt=n>>4 (512), kt=c>>3 (128)
//   lane = (n&7)*4 + (c&3), reg = ((n>>3)&1) + 2*((c>>2)&1)
// B fragment layout (per layer): B_perm[nt][kt][lane][reg], nt=n>>3 (128), kt=k>>3 (128)
//   lane = (n&7)*4 + (k&3), reg = (k>>2)&1

__device__ __forceinline__ float lk(float x){ return x >= 0.f ? x : SLOPE*x; }

__device__ __forceinline__ unsigned f2tf32(float f){
    unsigned r;
    asm("cvt.rna.tf32.f32 %0, %1;" : "=r"(r) : "f"(f));
    return r;
}

__device__ __forceinline__ float block_reduce_256(float v, float* sm){
    #pragma unroll
    for (int o=16;o>0;o>>=1) v += __shfl_xor_sync(0xffffffffu, v, o);
    int warp = threadIdx.x>>5, lane = threadIdx.x&31;
    if (lane==0) sm[warp]=v;
    __syncthreads();
    if (warp==0){
        v = (lane<8)? sm[lane] : 0.f;
        #pragma unroll
        for (int o=4;o>0;o>>=1) v += __shfl_xor_sync(0xffffffffu, v, o);
        if (lane==0) sm[0]=v;
    }
    __syncthreads();
    float r = sm[0];
    __syncthreads();
    return r;
}

__device__ __forceinline__ float block_reduce_max_256(float v, float* sm){
    #pragma unroll
    for (int o=16;o>0;o>>=1) v = fmaxf(v, __shfl_xor_sync(0xffffffffu, v, o));
    int warp = threadIdx.x>>5, lane = threadIdx.x&31;
    if (lane==0) sm[warp]=v;
    __syncthreads();
    if (warp==0){
        v = (lane<8)? sm[lane] : -1e30f;
        #pragma unroll
        for (int o=4;o>0;o>>=1) v = fmaxf(v, __shfl_xor_sync(0xffffffffu, v, o));
        if (lane==0) sm[0]=v;
    }
    __syncthreads();
    float r = sm[0];
    __syncthreads();
    return r;
}

// ---------------- launch 1: fused degree histogram + scan + CSR fill ----------------
__global__ void degfill_kernel(const int* __restrict__ ei){
    __shared__ int cnt[NNODES];
    __shared__ int sm[1024];
    int tid = threadIdx.x;
    for (int i=tid; i<NNODES; i+=1024) cnt[i]=0;
    __syncthreads();
    for (int e=tid; e<NEDGES; e+=1024) atomicAdd(&cnt[ei[NEDGES+e]], 1);
    __syncthreads();
    int base = tid*8;
    int loc[8]; int s=0;
    #pragma unroll
    for (int j=0;j<8;j++){ loc[j]=s; s += cnt[base+j]; }
    sm[tid]=s; __syncthreads();
    for (int off=1; off<1024; off<<=1){
        int t = (tid>=off) ? sm[tid-off] : 0;
        __syncthreads();
        sm[tid]+=t;
        __syncthreads();
    }
    int excl = sm[tid]-s;
    int st[8];
    #pragma unroll
    for (int j=0;j<8;j++){ st[j] = excl + loc[j]; g_rowptr[base+j] = st[j]; }
    if (tid==1023) g_rowptr[NNODES] = sm[1023];
    __syncthreads();
    #pragma unroll
    for (int j=0;j<8;j++) cnt[base+j] = st[j];
    __syncthreads();
    for (int e=tid; e<NEDGES; e+=1024){
        int v = ei[NEDGES+e];
        int p = atomicAdd(&cnt[v], 1);
        g_csru[p] = ei[e];
    }
}

// ---------------- launch 2: init copy + su(layer0) + weight conversion (fragment layout) ----------------
__global__ void init_su_kernel(const float* __restrict__ nf,
                               const float* __restrict__ a1,
                               const float* __restrict__ lw){
    int n = blockIdx.x, tid = threadIdx.x;
    float4 v = ((const float4*)nf)[(size_t)n*256+tid];
    ((float4*)g_feat)[(size_t)n*256+tid]=v;
    ((float4*)g_acc)[(size_t)n*256+tid]=v;
    // convert + permute weights: block n handles flat float4 index wi = n*128+tid (tid<128)
    if (tid < 128){
        size_t wi = (size_t)n*128 + tid;
        float4 wv = ((const float4*)lw)[wi];
        size_t f = wi*4;                       // flat float index into [4][1024][1024]
        int layer = (int)(f >> 20);
        int k  = (int)((f >> 10) & 1023);
        int nn = (int)(f & 1023);              // multiple of 4
        unsigned* dst = g_bw + (size_t)layer*1048576;
        int nt = nn>>3, kt = k>>3;
        size_t base = ((size_t)(nt*128 + kt)*32)*2;
        int reg = (k>>2)&1;
        float vals[4] = {wv.x, wv.y, wv.z, wv.w};
        #pragma unroll
        for (int i=0;i<4;i++){
            int lane = ((nn+i)&7)*4 + (k&3);
            dst[base + lane*2 + reg] = f2tf32(vals[i]);
        }
    }
    float4 a = ((const float4*)a1)[tid];
    float p = v.x*a.x + v.y*a.y + v.z*a.z + v.w*a.w;
    __shared__ float sm[32];
    p = block_reduce_256(p, sm);
    if (tid==0) g_su[n]=p;
}

// ---------------- launch 3: fused edge-softmax + aggregate; A stored in fragment layout ----------------
__global__ void smagg_kernel(){
    int n = blockIdx.x, tid = threadIdx.x;
    int s = g_rowptr[n], e = g_rowptr[n+1];
    __shared__ float s_w[256]; __shared__ int s_u[256];
    __shared__ float red[32];
    float m = -1e30f;
    for (int j=s+tid; j<e; j+=256) m = fmaxf(m, g_su[g_csru[j]]);
    m = block_reduce_max_256(m, red);
    float lsum = 0.f;
    float4 acc = make_float4(0.f,0.f,0.f,0.f);
    const float4* F4 = (const float4*)g_feat;
    for (int base=s; base<e; base+=256){
        int j = base + tid;
        if (j<e){
            int u = g_csru[j];
            float ex = __expf(g_su[u] - m);
            s_w[tid]=ex; s_u[tid]=u; lsum += ex;
        }
        __syncthreads();
        int cnt = min(256, e-base);
        for (int t=0;t<cnt;t++){
            float wv = s_w[t]; int u = s_u[t];
            float4 f = F4[(size_t)u*256 + tid];
            acc.x += wv*f.x; acc.y += wv*f.y; acc.z += wv*f.z; acc.w += wv*f.w;
        }
        __syncthreads();
    }
    float total = block_reduce_256(lsum, red);
    if (total > 0.f){
        float inv = 1.f/total;
        acc.x*=inv; acc.y*=inv; acc.z*=inv; acc.w*=inv;
    }
    // fragment-layout scatter: cols c = tid*4 .. +3 of node n
    int mt = n>>4, r = n&15;
    int kt = tid>>1;                       // (4*tid)>>3
    int reg = ((r>>3)&1) + ((tid&1)<<1);   // 2*((c>>2)&1) with c=4*tid
    size_t base = ((size_t)(mt*128 + kt)*32 + (r&7)*4)*4 + reg;
    float vals[4] = {acc.x, acc.y, acc.z, acc.w};
    #pragma unroll
    for (int i=0;i<4;i++)
        g_agg[base + i*4] = f2tf32(vals[i]);
}

// ---------------- launch 4: main tf32 GEMM, fragment-layout smem + cp.async ----------------
#define STG  3
#define ATSZ 4096          // unsigneds per A stage (128x32 tile)
#define BTSZ 4096          // unsigneds per B stage (32x128 tile)
#define MAIN_SMEM (STG*(ATSZ+BTSZ)*4)

__global__ void __launch_bounds__(256) mma_main_kernel(int layer){
    extern __shared__ unsigned dyn[];
    unsigned* AsB = dyn;
    unsigned* BsB = dyn + STG*ATSZ;
    const unsigned* A = g_agg;
    const unsigned* B = g_bw + (size_t)layer*1048576;

    const int tid = threadIdx.x;
    const int warp = tid>>5, lane = tid&31;
    const int wm = warp>>2, wn = warp&3;       // 2x4 warps, warp tile 64x32
    const int gid = lane>>2, qid = lane&3;
    const int mt0 = blockIdx.y*8;              // 8 m-tiles per block (BM=128)
    const int nt0 = blockIdx.x*16;             // 16 n-tiles per block (BN=128)

    // cp.async mapping (contiguous fragment chunks)
    const int achunk = tid>>3;                 // 0..31 : (mt 0..7, kt 0..3)
    const int amt = achunk>>2, akt = achunk&3;
    const int aoff = (tid&7)*16;
    const int bchunk = tid>>2;                 // 0..63 : (nt 0..15, kt 0..3)
    const int bnt = bchunk>>2, bkt = bchunk&3;
    const int boff = (tid&3)*16;

    auto issue = [&](int it){
        unsigned* As = AsB + (it%STG)*ATSZ;
        unsigned* Bs = BsB + (it%STG)*BTSZ;
        int kt0 = it*4;
        const unsigned* ga = A + ((size_t)((mt0+amt)*128 + kt0+akt))*128 + aoff;
        unsigned dsta = (unsigned)__cvta_generic_to_shared(&As[achunk*128 + aoff]);
        #pragma unroll
        for (int j=0;j<4;j++)
            asm volatile("cp.async.cg.shared.global [%0], [%1], 16;"
                         :: "r"(dsta + j*16), "l"(ga + j*4));
        const unsigned* gb = B + ((size_t)((nt0+bnt)*128 + kt0+bkt))*64 + boff;
        unsigned dstb = (unsigned)__cvta_generic_to_shared(&Bs[bchunk*64 + boff]);
        #pragma unroll
        for (int j=0;j<4;j++)
            asm volatile("cp.async.cg.shared.global [%0], [%1], 16;"
                         :: "r"(dstb + j*16), "l"(gb + j*4));
        asm volatile("cp.async.commit_group;" ::: "memory");
    };

    float acc[4][4][4];
    #pragma unroll
    for (int i=0;i<4;i++)
        #pragma unroll
        for (int j=0;j<4;j++)
            #pragma unroll
            for (int q=0;q<4;q++) acc[i][j][q]=0.f;

    issue(0); issue(1);

    const int NIT = DIMF/32;
    for (int it=0; it<NIT; it++){
        asm volatile("cp.async.wait_group 1;" ::: "memory");
        __syncthreads();
        if (it+2 < NIT) issue(it+2);
        const unsigned* curA = AsB + (it%STG)*ATSZ;
        const unsigned* curB = BsB + (it%STG)*BTSZ;
        #pragma unroll
        for (int kk=0; kk<4; kk++){
            uint4 af[4]; uint2 bf[4];
            #pragma unroll
            for (int i=0;i<4;i++)
                af[i] = *(const uint4*)&curA[((wm*4+i)*4 + kk)*128 + lane*4];
            #pragma unroll
            for (int j=0;j<4;j++)
                bf[j] = *(const uint2*)&curB[((wn*4+j)*4 + kk)*64 + lane*2];
            #pragma unroll
            for (int i=0;i<4;i++)
                #pragma unroll
                for (int j=0;j<4;j++){
                    asm volatile(
                        "mma.sync.aligned.m16n8k8.row.col.f32.tf32.tf32.f32 "
                        "{%0,%1,%2,%3}, {%4,%5,%6,%7}, {%8,%9}, {%0,%1,%2,%3};"
                        : "+f"(acc[i][j][0]), "+f"(acc[i][j][1]),
                          "+f"(acc[i][j][2]), "+f"(acc[i][j][3])
                        : "r"(af[i].x), "r"(af[i].y), "r"(af[i].z), "r"(af[i].w),
                          "r"(bf[j].x), "r"(bf[j].y));
                }
        }
    }
    const int bm0 = blockIdx.y*128, bn0 = blockIdx.x*128;
    #pragma unroll
    for (int i=0;i<4;i++){
        int r0 = bm0 + wm*64 + i*16 + gid;
        #pragma unroll
        for (int j=0;j<4;j++){
            int cc = bn0 + wn*32 + j*8 + qid*2;
            float2 v0, v1;
            v0.x = acc[i][j][0]; v0.y = acc[i][j][1];
            v1.x = acc[i][j][2]; v1.y = acc[i][j][3];
            *(float2*)(g_gemm + (size_t) r0   *DIMF + cc) = v0;
            *(float2*)(g_gemm + (size_t)(r0+8)*DIMF + cc) = v1;
        }
    }
}

// ---------------- hid GEMM (small; register-staged path, unchanged) ----------------
template<int BM,int BN,int BK,int WM,int WN,bool BIAS>
__device__ __forceinline__ void mma_body(
        const float* __restrict__ A, const float* __restrict__ B,
        float* __restrict__ C, int N, int K,
        float alpha, const float* __restrict__ bias,
        unsigned* As, unsigned* Bs){
    constexpr int MT = WM/16, NT = WN/8, KT = BK/8;
    constexpr int WARPS_N = BN/WN;
    constexpr int PA = BK+4;
    constexpr int PB = BN+8;
    constexpr int AREG = BM*BK/1024;
    constexpr int BREG = BK*BN/1024;

    const int tid = threadIdx.x;
    const int warp = tid>>5, lane = tid&31;
    const int wm = warp / WARPS_N, wn = warp % WARPS_N;
    const int gid = lane>>2, qid = lane&3;
    const int bm0 = blockIdx.y*BM, bn0 = blockIdx.x*BN;

    float4 ra[AREG], rb[BREG];

    auto ldg_tile = [&](int k0){
        #pragma unroll
        for (int a=0;a<AREG;a++){
            int i = tid*4 + a*1024;
            int r = i/BK, c = i%BK;
            ra[a] = *(const float4*)(A + (size_t)(bm0+r)*K + k0 + c);
        }
        #pragma unroll
        for (int b=0;b<BREG;b++){
            int i = tid*4 + b*1024;
            int r = i/BN, c = i%BN;
            rb[b] = *(const float4*)(B + (size_t)(k0+r)*N + bn0 + c);
        }
    };
    auto sts_tile = [&](){
        #pragma unroll
        for (int a=0;a<AREG;a++){
            int i = tid*4 + a*1024;
            int r = i/BK, c = i%BK;
            uint4 p;
            p.x=f2tf32(ra[a].x); p.y=f2tf32(ra[a].y);
            p.z=f2tf32(ra[a].z); p.w=f2tf32(ra[a].w);
            *(uint4*)&As[r*PA+c] = p;
        }
        #pragma unroll
        for (int b=0;b<BREG;b++){
            int i = tid*4 + b*1024;
            int r = i/BN, c = i%BN;
            uint4 p;
            p.x=f2tf32(rb[b].x); p.y=f2tf32(rb[b].y);
            p.z=f2tf32(rb[b].z); p.w=f2tf32(rb[b].w);
            *(uint4*)&Bs[r*PB+c] = p;
        }
    };

    float acc[MT][NT][4];
    #pragma unroll
    for (int i=0;i<MT;i++)
        #pragma unroll
        for (int j=0;j<NT;j++)
            #pragma unroll
            for (int q=0;q<4;q++) acc[i][j][q]=0.f;

    ldg_tile(0);
    sts_tile();
    __syncthreads();

    const int NIT = K/BK;
    for (int it=0; it<NIT; it++){
        if (it+1 < NIT) ldg_tile((it+1)*BK);
        #pragma unroll
        for (int kk=0; kk<KT; kk++){
            unsigned af[MT][4], bf[NT][2];
            #pragma unroll
            for (int i=0;i<MT;i++){
                int r0 = wm*WM + i*16 + gid;
                int c0 = kk*8 + qid;
                af[i][0]=As[ r0   *PA + c0  ];
                af[i][1]=As[(r0+8)*PA + c0  ];
                af[i][2]=As[ r0   *PA + c0+4];
                af[i][3]=As[(r0+8)*PA + c0+4];
            }
            #pragma unroll
            for (int j=0;j<NT;j++){
                int cc = wn*WN + j*8 + gid;
                bf[j][0]=Bs[(kk*8+qid  )*PB + cc];
                bf[j][1]=Bs[(kk*8+qid+4)*PB + cc];
            }
            #pragma unroll
            for (int i=0;i<MT;i++)
                #pragma unroll
                for (int j=0;j<NT;j++){
                    asm volatile(
                        "mma.sync.aligned.m16n8k8.row.col.f32.tf32.tf32.f32 "
                        "{%0,%1,%2,%3}, {%4,%5,%6,%7}, {%8,%9}, {%0,%1,%2,%3};"
                        : "+f"(acc[i][j][0]), "+f"(acc[i][j][1]),
                          "+f"(acc[i][j][2]), "+f"(acc[i][j][3])
                        : "r"(af[i][0]), "r"(af[i][1]), "r"(af[i][2]), "r"(af[i][3]),
                          "r"(bf[j][0]), "r"(bf[j][1]));
                }
        }
        __syncthreads();
        if (it+1 < NIT){
            sts_tile();
            __syncthreads();
        }
    }
    #pragma unroll
    for (int i=0;i<MT;i++){
        int r0 = bm0 + wm*WM + i*16 + gid;
        #pragma unroll
        for (int j=0;j<NT;j++){
            int cc = bn0 + wn*WN + j*8 + qid*2;
            float b0 = BIAS ? bias[cc] : 0.f;
            float b1 = BIAS ? bias[cc+1] : 0.f;
            float2 v0, v1;
            v0.x = alpha*acc[i][j][0] + b0;
            v0.y = alpha*acc[i][j][1] + b1;
            v1.x = alpha*acc[i][j][2] + b0;
            v1.y = alpha*acc[i][j][3] + b1;
            *(float2*)(C + (size_t) r0   *N + cc) = v0;
            *(float2*)(C + (size_t)(r0+8)*N + cc) = v1;
        }
    }
}

#define HID_SMEM ((64*36 + 32*72)*4)
__global__ void __launch_bounds__(256) mma_hid_kernel(const float* __restrict__ Bw,
                                                      const float* __restrict__ bias){
    extern __shared__ unsigned dyn[];
    unsigned* As = dyn;
    unsigned* Bs = dyn + 64*36;
    mma_body<64,64,32,16,32,true>(g_acc, Bw, g_nf, HID, DIMF,
                                  0.2f, bias, As, Bs);
}

// ---------------- launch 5 (per layer): LN + leaky + feat/acc update + next su ----------------
__global__ void ln_su_kernel(const float* __restrict__ linb,
                             const float* __restrict__ lng,
                             const float* __restrict__ lnb,
                             const float* __restrict__ a1next){
    int n = blockIdx.x, tid = threadIdx.x;
    float4 x = ((const float4*)g_gemm)[(size_t)n*256+tid];
    float4 bb = ((const float4*)linb)[tid];
    x.x+=bb.x; x.y+=bb.y; x.z+=bb.z; x.w+=bb.w;
    __shared__ float sm[32];
    float s = x.x+x.y+x.z+x.w;
    s = block_reduce_256(s, sm);
    float mu = s*(1.f/1024.f);
    float d0=x.x-mu, d1=x.y-mu, d2=x.z-mu, d3=x.w-mu;
    float q = d0*d0+d1*d1+d2*d2+d3*d3;
    q = block_reduce_256(q, sm);
    float r = rsqrtf(q*(1.f/1024.f)+EPSV);
    float4 gg = ((const float4*)lng)[tid];
    float4 b2 = ((const float4*)lnb)[tid];
    float4 y;
    y.x = lk(gg.x*d0*r + b2.x);
    y.y = lk(gg.y*d1*r + b2.y);
    y.z = lk(gg.z*d2*r + b2.z);
    y.w = lk(gg.w*d3*r + b2.w);
    ((float4*)g_feat)[(size_t)n*256+tid] = y;
    float4 a = ((float4*)g_acc)[(size_t)n*256+tid];
    a.x+=y.x; a.y+=y.y; a.z+=y.z; a.w+=y.w;
    ((float4*)g_acc)[(size_t)n*256+tid] = a;
    if (a1next){
        float4 av = ((const float4*)a1next)[tid];
        float p = y.x*av.x + y.y*av.y + y.z*av.z + y.w*av.w;
        p = block_reduce_256(p, sm);
        if (tid==0) g_su[n]=p;
    }
}

// ---------------- zeroing (surface/ns branch only) ----------------
__global__ void zero_kernel(){
    int i = blockIdx.x*256 + threadIdx.x;
    if (i < NNODES*HID) g_ressum[i] = 0.f;
    if (i < NNODES) g_rescnt[i]=0.f;
    if (i < 2*HID){ g_stats[i]=0.f; g_stats2[i]=0.f; }
    if (i < NGRAPH*HID) g_nssum[i]=0.f;
    if (i < NGRAPH) g_nscnt[i]=0.f;
}

// ---------------- surface path ----------------
__global__ void surf_lin_kernel(const float* __restrict__ sf,
                                const float* __restrict__ W,
                                const float* __restrict__ b){
    int c  = threadIdx.x & 63;
    int ry = threadIdx.x >> 6;
    int row0 = blockIdx.x * 64;
    float w0=W[c], w1=W[64+c], w2=W[128+c], bc=b[c];
    float ls=0.f, lss=0.f;
    for (int r=ry; r<64; r+=4){
        int row = row0 + r;
        float x0=sf[row*3], x1=sf[row*3+1], x2=sf[row*3+2];
        float y = fmaf(x0,w0, fmaf(x1,w1, fmaf(x2,w2, bc)));
        g_surfy[row*64+c]=y; ls+=y; lss+=y*y;
    }
    __shared__ float ss[256], sq[256];
    ss[threadIdx.x]=ls; sq[threadIdx.x]=lss;
    __syncthreads();
    if (ry==0){
        float t  = ss[c]+ss[64+c]+ss[128+c]+ss[192+c];
        float t2 = sq[c]+sq[64+c]+sq[128+c]+sq[192+c];
        atomicAdd(&g_stats[c], t);
        atomicAdd(&g_stats[64+c], t2);
    }
}

__global__ void finalize_stats_kernel(int which, float n){
    float* st = which ? g_stats2 : g_stats;
    int c = threadIdx.x;
    float mu  = st[c] / n;
    float var = st[64+c]/n - mu*mu;
    st[c]   = mu;
    st[64+c]= rsqrtf(fmaxf(var,0.f)+EPSV);
}

__global__ void surf_norm_scatter_kernel(const int* __restrict__ surf_res,
                                         const float* __restrict__ g,
                                         const float* __restrict__ beta){
    int idx = blockIdx.x*256 + threadIdx.x;
    int row = idx >> 6, c = idx & 63;
    float y = g_surfy[idx];
    float v = lk(g[c]*(y - g_stats[c])*g_stats[64+c] + beta[c]);
    int t = surf_res[row];
    atomicAdd(&g_ressum[t*64 + c], v);
    if (c==0) atomicAdd(&g_rescnt[t], 1.f);
}

__global__ void gather_s_kernel(const int* __restrict__ uniq){
    int idx = blockIdx.x*256 + threadIdx.x;
    int i = idx >> 6, c = idx & 63;
    int u = uniq[i];
    g_s[idx] = g_ressum[u*64+c] / fmaxf(g_rescnt[u], 1.f);
}

// ---------------- final heads ----------------
__global__ void prot_kernel(const float* __restrict__ g,
                            const float* __restrict__ b,
                            float* __restrict__ out){
    int gr = blockIdx.x, c = threadIdx.x;
    const float* base = g_nf + (size_t)gr*512*64;
    float s = 0.f;
    for (int r=0;r<512;r++) s += base[r*64+c];
    float x = s*(1.f/512.f);
    __shared__ float sm[64];
    __shared__ float s_mu, s_r;
    sm[c]=x; __syncthreads();
    if (c==0){ float t=0.f; for (int i=0;i<64;i++) t+=sm[i]; s_mu=t*(1.f/64.f); }
    __syncthreads();
    float d = x - s_mu;
    sm[c]=d*d; __syncthreads();
    if (c==0){ float t=0.f; for (int i=0;i<64;i++) t+=sm[i]; s_r=rsqrtf(t*(1.f/64.f)+EPSV); }
    __syncthreads();
    out[gr*64+c] = lk(g[c]*d*s_r + b[c]);
}

__global__ void ns_a_kernel(const int* __restrict__ uniq,
                            const float* __restrict__ dw,
                            const float* __restrict__ db){
    __shared__ float s_wd[128*64];
    __shared__ float z_s[128];
    int tid = threadIdx.x;
    for (int i=tid; i<128*64; i+=64) s_wd[i]=dw[i];
    float bc = db[tid];
    float ls=0.f, lss=0.f;
    __syncthreads();
    int row0 = blockIdx.x*64;
    for (int r=0;r<64;r++){
        int row = row0 + r;
        if (row >= NUNIQ) break;
        z_s[tid]      = g_nf[(size_t)uniq[row]*64 + tid];
        z_s[64+tid]   = g_s[(size_t)row*64 + tid];
        __syncthreads();
        float y = bc;
        #pragma unroll 8
        for (int k=0;k<128;k++) y = fmaf(z_s[k], s_wd[k*64+tid], y);
        g_y2[(size_t)row*64+tid] = y;
        ls += y; lss += y*y;
        __syncthreads();
    }
    atomicAdd(&g_stats2[tid], ls);
    atomicAdd(&g_stats2[64+tid], lss);
}

__global__ void ns_norm_scatter_kernel(const int* __restrict__ res_batch,
                                       const float* __restrict__ g,
                                       const float* __restrict__ beta){
    int idx = blockIdx.x*256 + threadIdx.x;
    int row = idx >> 6, c = idx & 63;
    float y = g_y2[idx];
    float v = lk(g[c]*(y - g_stats2[c])*g_stats2[64+c] + beta[c]);
    int t = res_batch[row];
    atomicAdd(&g_nssum[t*64 + c], v);
    if (c==0) atomicAdd(&g_nscnt[t], 1.f);
}

__global__ void ns_final_kernel(const float* __restrict__ bng,
                                const float* __restrict__ bnb,
                                float* __restrict__ out){
    int tid = threadIdx.x;
    int gr = tid >> 6, c = tid & 63;
    float v = g_nssum[tid] / fmaxf(g_nscnt[gr], 1.f);
    __shared__ float sm[1024];
    __shared__ float s_mu[64], s_r[64];
    sm[tid]=v; __syncthreads();
    if (gr==0){
        float t=0.f, t2=0.f;
        for (int r=0;r<16;r++){ float x=sm[r*64+c]; t+=x; t2+=x*x; }
        float mu = t*(1.f/16.f);
        s_mu[c]=mu;
        s_r[c]=rsqrtf(fmaxf(t2*(1.f/16.f)-mu*mu,0.f)+EPSV);
    }
    __syncthreads();
    out[16*64 + tid] = lk(bng[c]*(v - s_mu[c])*s_r[c] + bnb[c]);
}

// ---------------- host ----------------
extern "C" void kernel_launch(void* const* d_in, const int* in_sizes, int n_in,
                              void* d_out, int out_size){
    const int*   ei         = (const int*)  d_in[0];
    const float* n_feats    = (const float*)d_in[1];
    const float* surf_feats = (const float*)d_in[3];
    const int*   surf_res   = (const int*)  d_in[4];
    const int*   res_batch  = (const int*)  d_in[5];
    const int*   uniq       = (const int*)  d_in[6];
    const float* surf_up_w  = (const float*)d_in[7];
    const float* surf_up_b  = (const float*)d_in[8];
    const float* surf_up_g  = (const float*)d_in[9];
    const float* surf_up_be = (const float*)d_in[10];
    const float* a_w        = (const float*)d_in[11];
    const float* lin_w      = (const float*)d_in[12];
    const float* lin_b      = (const float*)d_in[13];
    const float* ln_g       = (const float*)d_in[14];
    const float* ln_b       = (const float*)d_in[15];
    const float* hid_w      = (const float*)d_in[16];
    const float* hid_b      = (const float*)d_in[17];
    const float* down_w     = (const float*)d_in[18];
    const float* down_b     = (const float*)d_in[19];
    const float* down_g     = (const float*)d_in[20];
    const float* down_be    = (const float*)d_in[21];
    const float* prot_ln_g  = (const float*)d_in[22];
    const float* prot_ln_b  = (const float*)d_in[23];
    const float* surf_bn_g  = (const float*)d_in[24];
    const float* surf_bn_b  = (const float*)d_in[25];
    float* out = (float*)d_out;

    cudaFuncSetAttribute(mma_main_kernel,
                         cudaFuncAttributeMaxDynamicSharedMemorySize, MAIN_SMEM);
    cudaFuncSetAttribute(mma_hid_kernel,
                         cudaFuncAttributeMaxDynamicSharedMemorySize, HID_SMEM);

    degfill_kernel<<<1, 1024>>>(ei);                                // 1
    init_su_kernel<<<NNODES, 256>>>(n_feats, a_w, lin_w);           // 2

    for (int l=0; l<4; l++){
        smagg_kernel<<<NNODES, 256>>>();                            // 3
        mma_main_kernel<<<dim3(DIMF/128, NNODES/128), 256, MAIN_SMEM>>>(l); // 4 <- profiled
        const float* a1n = (l<3) ? (a_w + (size_t)(l+1)*2*DIMF) : nullptr;
        ln_su_kernel<<<NNODES, 256>>>(lin_b + (size_t)l*DIMF,       // 5
                                      ln_g + (size_t)l*DIMF,
                                      ln_b + (size_t)l*DIMF, a1n);
    }

    mma_hid_kernel<<<dim3(1, NNODES/64), 256, HID_SMEM>>>(hid_w, hid_b);
    prot_kernel<<<NGRAPH, 64>>>(prot_ln_g, prot_ln_b, out);

    zero_kernel<<<(NNODES*HID)/256, 256>>>();
    surf_lin_kernel<<<NSURF/64, 256>>>(surf_feats, surf_up_w, surf_up_b);
    finalize_stats_kernel<<<1,64>>>(0, (float)NSURF);
    surf_norm_scatter_kernel<<<(NSURF*HID)/256, 256>>>(surf_res, surf_up_g, surf_up_be);
    gather_s_kernel<<<(NUNIQ*HID)/256, 256>>>(uniq);

    ns_a_kernel<<<(NUNIQ+63)/64, 64>>>(uniq, down_w, down_b);
    finalize_stats_kernel<<<1,64>>>(1, (float)NUNIQ);
    ns_norm_scatter_kernel<<<(NUNIQ*HID)/256, 256>>>(res_batch, down_g, down_be);
    ns_final_kernel<<<1,1024>>>(surf_bn_g, surf_bn_b, out);
}

// round 8
// speedup vs baseline: 1.1494x; 1.1494x over previous
#include <cuda_runtime.h>
#include <math.h>

#define NNODES 8192
#define NEDGES 65536
#define NSURF  40000
#define NUNIQ  6000
#define NGRAPH 16
#define DIMF   1024
#define HID    64
#define EPSV   1e-5f
#define SLOPE  0.01f

// ---------------- scratch (device globals; referenced ONLY in device code) ----------------
__device__ float    g_feat[NNODES*DIMF];
__device__ float    g_acc [NNODES*DIMF];
__device__ unsigned g_agg [NNODES*DIMF];     // tf32 bits (A operand, row-major)
__device__ unsigned g_bw  [4*DIMF*DIMF];     // tf32 bits of lin_w (row-major, 4 layers)
__device__ float    g_gemm[NNODES*DIMF];
__device__ float    g_surfy[NSURF*HID];
__device__ float    g_ressum[NNODES*HID];
__device__ float    g_rescnt[NNODES];
__device__ float    g_s[NUNIQ*HID];
__device__ float    g_su[NNODES];
__device__ int      g_csru[NEDGES];
__device__ int      g_rowptr[NNODES+1];
__device__ float    g_stats [2*HID];
__device__ float    g_stats2[2*HID];
__device__ float    g_nf[NNODES*HID];
__device__ float    g_y2[NUNIQ*HID];
__device__ float    g_nssum[NGRAPH*HID];
__device__ float    g_nscnt[NGRAPH];

__device__ __forceinline__ float lk(float x){ return x >= 0.f ? x : SLOPE*x; }

__device__ __forceinline__ unsigned f2tf32(float f){
    unsigned r;
    asm("cvt.rna.tf32.f32 %0, %1;" : "=r"(r) : "f"(f));
    return r;
}

__device__ __forceinline__ float block_reduce_256(float v, float* sm){
    #pragma unroll
    for (int o=16;o>0;o>>=1) v += __shfl_xor_sync(0xffffffffu, v, o);
    int warp = threadIdx.x>>5, lane = threadIdx.x&31;
    if (lane==0) sm[warp]=v;
    __syncthreads();
    if (warp==0){
        v = (lane<8)? sm[lane] : 0.f;
        #pragma unroll
        for (int o=4;o>0;o>>=1) v += __shfl_xor_sync(0xffffffffu, v, o);
        if (lane==0) sm[0]=v;
    }
    __syncthreads();
    float r = sm[0];
    __syncthreads();
    return r;
}

__device__ __forceinline__ float block_reduce_max_256(float v, float* sm){
    #pragma unroll
    for (int o=16;o>0;o>>=1) v = fmaxf(v, __shfl_xor_sync(0xffffffffu, v, o));
    int warp = threadIdx.x>>5, lane = threadIdx.x&31;
    if (lane==0) sm[warp]=v;
    __syncthreads();
    if (warp==0){
        v = (lane<8)? sm[lane] : -1e30f;
        #pragma unroll
        for (int o=4;o>0;o>>=1) v = fmaxf(v, __shfl_xor_sync(0xffffffffu, v, o));
        if (lane==0) sm[0]=v;
    }
    __syncthreads();
    float r = sm[0];
    __syncthreads();
    return r;
}

// ---------------- launch 1: fused degree histogram + scan + CSR fill ----------------
__global__ void degfill_kernel(const int* __restrict__ ei){
    __shared__ int cnt[NNODES];
    __shared__ int sm[1024];
    int tid = threadIdx.x;
    for (int i=tid; i<NNODES; i+=1024) cnt[i]=0;
    __syncthreads();
    for (int e=tid; e<NEDGES; e+=1024) atomicAdd(&cnt[ei[NEDGES+e]], 1);
    __syncthreads();
    int base = tid*8;
    int loc[8]; int s=0;
    #pragma unroll
    for (int j=0;j<8;j++){ loc[j]=s; s += cnt[base+j]; }
    sm[tid]=s; __syncthreads();
    for (int off=1; off<1024; off<<=1){
        int t = (tid>=off) ? sm[tid-off] : 0;
        __syncthreads();
        sm[tid]+=t;
        __syncthreads();
    }
    int excl = sm[tid]-s;
    int st[8];
    #pragma unroll
    for (int j=0;j<8;j++){ st[j] = excl + loc[j]; g_rowptr[base+j] = st[j]; }
    if (tid==1023) g_rowptr[NNODES] = sm[1023];
    __syncthreads();
    #pragma unroll
    for (int j=0;j<8;j++) cnt[base+j] = st[j];
    __syncthreads();
    for (int e=tid; e<NEDGES; e+=1024){
        int v = ei[NEDGES+e];
        int p = atomicAdd(&cnt[v], 1);
        g_csru[p] = ei[e];
    }
}

// ---------------- launch 2: init copy + su(layer0) + weight conversion (row-major) ----------------
__global__ void init_su_kernel(const float* __restrict__ nf,
                               const float* __restrict__ a1,
                               const float* __restrict__ lw){
    int n = blockIdx.x, tid = threadIdx.x;
    float4 v = ((const float4*)nf)[(size_t)n*256+tid];
    ((float4*)g_feat)[(size_t)n*256+tid]=v;
    ((float4*)g_acc)[(size_t)n*256+tid]=v;
    if (tid < 128){
        size_t wi = (size_t)n*128 + tid;
        float4 wv = ((const float4*)lw)[wi];
        uint4 p;
        p.x=f2tf32(wv.x); p.y=f2tf32(wv.y); p.z=f2tf32(wv.z); p.w=f2tf32(wv.w);
        ((uint4*)g_bw)[wi] = p;
    }
    float4 a = ((const float4*)a1)[tid];
    float p = v.x*a.x + v.y*a.y + v.z*a.z + v.w*a.w;
    __shared__ float sm[32];
    p = block_reduce_256(p, sm);
    if (tid==0) g_su[n]=p;
}

// ---------------- launch 3: fused edge-softmax + aggregate; stores tf32 bits ----------------
__global__ void smagg_kernel(){
    int n = blockIdx.x, tid = threadIdx.x;
    int s = g_rowptr[n], e = g_rowptr[n+1];
    __shared__ float s_w[256]; __shared__ int s_u[256];
    __shared__ float red[32];
    float m = -1e30f;
    for (int j=s+tid; j<e; j+=256) m = fmaxf(m, g_su[g_csru[j]]);
    m = block_reduce_max_256(m, red);
    float lsum = 0.f;
    float4 acc = make_float4(0.f,0.f,0.f,0.f);
    const float4* F4 = (const float4*)g_feat;
    for (int base=s; base<e; base+=256){
        int j = base + tid;
        if (j<e){
            int u = g_csru[j];
            float ex = __expf(g_su[u] - m);
            s_w[tid]=ex; s_u[tid]=u; lsum += ex;
        }
        __syncthreads();
        int cnt = min(256, e-base);
        for (int t=0;t<cnt;t++){
            float wv = s_w[t]; int u = s_u[t];
            float4 f = F4[(size_t)u*256 + tid];
            acc.x += wv*f.x; acc.y += wv*f.y; acc.z += wv*f.z; acc.w += wv*f.w;
        }
        __syncthreads();
    }
    float total = block_reduce_256(lsum, red);
    if (total > 0.f){
        float inv = 1.f/total;
        acc.x*=inv; acc.y*=inv; acc.z*=inv; acc.w*=inv;
    }
    uint4 p;
    p.x=f2tf32(acc.x); p.y=f2tf32(acc.y); p.z=f2tf32(acc.z); p.w=f2tf32(acc.w);
    ((uint4*)g_agg)[(size_t)n*256 + tid] = p;
}

// ---------------- launch 4: main tf32 GEMM, cp.async + register frag double-buffer ----------------
#define STG  3
#define PA_  36
#define PB_  136
#define ASZ_ (128*PA_)
#define BSZ_ (32*PB_)
#define MAIN_SMEM (STG*(ASZ_+BSZ_)*4)

__global__ void __launch_bounds__(256,2) mma_main_kernel(int layer){
    extern __shared__ unsigned dyn[];
    unsigned* AsB = dyn;
    unsigned* BsB = dyn + STG*ASZ_;
    const unsigned* A = g_agg;
    const unsigned* B = g_bw + (size_t)layer*DIMF*DIMF;

    const int tid = threadIdx.x;
    const int warp = tid>>5, lane = tid&31;
    const int wm = warp>>2, wn = warp&3;         // 2x4 warps, warp tile 64x32
    const int gid = lane>>2, qid = lane&3;
    const int bm0 = blockIdx.y*128, bn0 = blockIdx.x*128;

    const int ca = (tid*4)&31,  ra0 = tid>>3;
    const int cb = (tid*4)&127, rb0 = tid>>5;

    auto issue = [&](int it){
        unsigned* As = AsB + (it%STG)*ASZ_;
        unsigned* Bs = BsB + (it%STG)*BSZ_;
        int k0 = it*32;
        #pragma unroll
        for (int a=0;a<4;a++){
            int r = ra0 + a*32;
            unsigned dst = (unsigned)__cvta_generic_to_shared(&As[r*PA_+ca]);
            asm volatile("cp.async.cg.shared.global [%0], [%1], 16;"
                         :: "r"(dst), "l"(A + (size_t)(bm0+r)*DIMF + k0 + ca));
        }
        #pragma unroll
        for (int b=0;b<4;b++){
            int r = rb0 + b*8;
            unsigned dst = (unsigned)__cvta_generic_to_shared(&Bs[r*PB_+cb]);
            asm volatile("cp.async.cg.shared.global [%0], [%1], 16;"
                         :: "r"(dst), "l"(B + (size_t)(k0+r)*DIMF + bn0 + cb));
        }
        asm volatile("cp.async.commit_group;" ::: "memory");
    };

    float acc[4][4][4];
    #pragma unroll
    for (int i=0;i<4;i++)
        #pragma unroll
        for (int j=0;j<4;j++)
            #pragma unroll
            for (int q=0;q<4;q++) acc[i][j][q]=0.f;

    issue(0); issue(1);

    unsigned af[2][4][4], bf[2][4][2];

    const int NIT = DIMF/32;
    for (int it=0; it<NIT; it++){
        asm volatile("cp.async.wait_group 1;" ::: "memory");
        __syncthreads();
        if (it+2 < NIT) issue(it+2);
        const unsigned* curA = AsB + (it%STG)*ASZ_;
        const unsigned* curB = BsB + (it%STG)*BSZ_;

        // preload fragments for kk=0 into buffer 0
        #pragma unroll
        for (int i=0;i<4;i++){
            int r0 = wm*64 + i*16 + gid;
            af[0][i][0]=curA[ r0   *PA_ + qid  ];
            af[0][i][1]=curA[(r0+8)*PA_ + qid  ];
            af[0][i][2]=curA[ r0   *PA_ + qid+4];
            af[0][i][3]=curA[(r0+8)*PA_ + qid+4];
        }
        #pragma unroll
        for (int j=0;j<4;j++){
            int cc = wn*32 + j*8 + gid;
            bf[0][j][0]=curB[(qid  )*PB_ + cc];
            bf[0][j][1]=curB[(qid+4)*PB_ + cc];
        }

        #pragma unroll
        for (int kk=0; kk<4; kk++){
            const int cur = kk&1, nxt = cur^1;
            if (kk<3){
                // prefetch kk+1 fragments; MMAs below hide the LDS latency
                int c0 = (kk+1)*8 + qid;
                #pragma unroll
                for (int i=0;i<4;i++){
                    int r0 = wm*64 + i*16 + gid;
                    af[nxt][i][0]=curA[ r0   *PA_ + c0  ];
                    af[nxt][i][1]=curA[(r0+8)*PA_ + c0  ];
                    af[nxt][i][2]=curA[ r0   *PA_ + c0+4];
                    af[nxt][i][3]=curA[(r0+8)*PA_ + c0+4];
                }
                #pragma unroll
                for (int j=0;j<4;j++){
                    int cc = wn*32 + j*8 + gid;
                    bf[nxt][j][0]=curB[((kk+1)*8+qid  )*PB_ + cc];
                    bf[nxt][j][1]=curB[((kk+1)*8+qid+4)*PB_ + cc];
                }
            }
            #pragma unroll
            for (int i=0;i<4;i++)
                #pragma unroll
                for (int j=0;j<4;j++){
                    asm volatile(
                        "mma.sync.aligned.m16n8k8.row.col.f32.tf32.tf32.f32 "
                        "{%0,%1,%2,%3}, {%4,%5,%6,%7}, {%8,%9}, {%0,%1,%2,%3};"
                        : "+f"(acc[i][j][0]), "+f"(acc[i][j][1]),
                          "+f"(acc[i][j][2]), "+f"(acc[i][j][3])
                        : "r"(af[cur][i][0]), "r"(af[cur][i][1]),
                          "r"(af[cur][i][2]), "r"(af[cur][i][3]),
                          "r"(bf[cur][j][0]), "r"(bf[cur][j][1]));
                }
        }
    }
    #pragma unroll
    for (int i=0;i<4;i++){
        int r0 = bm0 + wm*64 + i*16 + gid;
        #pragma unroll
        for (int j=0;j<4;j++){
            int cc = bn0 + wn*32 + j*8 + qid*2;
            float2 v0, v1;
            v0.x = acc[i][j][0]; v0.y = acc[i][j][1];
            v1.x = acc[i][j][2]; v1.y = acc[i][j][3];
            *(float2*)(g_gemm + (size_t) r0   *DIMF + cc) = v0;
            *(float2*)(g_gemm + (size_t)(r0+8)*DIMF + cc) = v1;
        }
    }
}

// ---------------- hid GEMM (small; register-staged path) ----------------
template<int BM,int BN,int BK,int WM,int WN,bool BIAS>
__device__ __forceinline__ void mma_body(
        const float* __restrict__ A, const float* __restrict__ B,
        float* __restrict__ C, int N, int K,
        float alpha, const float* __restrict__ bias,
        unsigned* As, unsigned* Bs){
    constexpr int MT = WM/16, NT = WN/8, KT = BK/8;
    constexpr int WARPS_N = BN/WN;
    constexpr int PA = BK+4;
    constexpr int PB = BN+8;
    constexpr int AREG = BM*BK/1024;
    constexpr int BREG = BK*BN/1024;

    const int tid = threadIdx.x;
    const int warp = tid>>5, lane = tid&31;
    const int wm = warp / WARPS_N, wn = warp % WARPS_N;
    const int gid = lane>>2, qid = lane&3;
    const int bm0 = blockIdx.y*BM, bn0 = blockIdx.x*BN;

    float4 ra[AREG], rb[BREG];

    auto ldg_tile = [&](int k0){
        #pragma unroll
        for (int a=0;a<AREG;a++){
            int i = tid*4 + a*1024;
            int r = i/BK, c = i%BK;
            ra[a] = *(const float4*)(A + (size_t)(bm0+r)*K + k0 + c);
        }
        #pragma unroll
        for (int b=0;b<BREG;b++){
            int i = tid*4 + b*1024;
            int r = i/BN, c = i%BN;
            rb[b] = *(const float4*)(B + (size_t)(k0+r)*N + bn0 + c);
        }
    };
    auto sts_tile = [&](){
        #pragma unroll
        for (int a=0;a<AREG;a++){
            int i = tid*4 + a*1024;
            int r = i/BK, c = i%BK;
            uint4 p;
            p.x=f2tf32(ra[a].x); p.y=f2tf32(ra[a].y);
            p.z=f2tf32(ra[a].z); p.w=f2tf32(ra[a].w);
            *(uint4*)&As[r*PA+c] = p;
        }
        #pragma unroll
        for (int b=0;b<BREG;b++){
            int i = tid*4 + b*1024;
            int r = i/BN, c = i%BN;
            uint4 p;
            p.x=f2tf32(rb[b].x); p.y=f2tf32(rb[b].y);
            p.z=f2tf32(rb[b].z); p.w=f2tf32(rb[b].w);
            *(uint4*)&Bs[r*PB+c] = p;
        }
    };

    float acc[MT][NT][4];
    #pragma unroll
    for (int i=0;i<MT;i++)
        #pragma unroll
        for (int j=0;j<NT;j++)
            #pragma unroll
            for (int q=0;q<4;q++) acc[i][j][q]=0.f;

    ldg_tile(0);
    sts_tile();
    __syncthreads();

    const int NIT = K/BK;
    for (int it=0; it<NIT; it++){
        if (it+1 < NIT) ldg_tile((it+1)*BK);
        #pragma unroll
        for (int kk=0; kk<KT; kk++){
            unsigned af[MT][4], bf[NT][2];
            #pragma unroll
            for (int i=0;i<MT;i++){
                int r0 = wm*WM + i*16 + gid;
                int c0 = kk*8 + qid;
                af[i][0]=As[ r0   *PA + c0  ];
                af[i][1]=As[(r0+8)*PA + c0  ];
                af[i][2]=As[ r0   *PA + c0+4];
                af[i][3]=As[(r0+8)*PA + c0+4];
            }
            #pragma unroll
            for (int j=0;j<NT;j++){
                int cc = wn*WN + j*8 + gid;
                bf[j][0]=Bs[(kk*8+qid  )*PB + cc];
                bf[j][1]=Bs[(kk*8+qid+4)*PB + cc];
            }
            #pragma unroll
            for (int i=0;i<MT;i++)
                #pragma unroll
                for (int j=0;j<NT;j++){
                    asm volatile(
                        "mma.sync.aligned.m16n8k8.row.col.f32.tf32.tf32.f32 "
                        "{%0,%1,%2,%3}, {%4,%5,%6,%7}, {%8,%9}, {%0,%1,%2,%3};"
                        : "+f"(acc[i][j][0]), "+f"(acc[i][j][1]),
                          "+f"(acc[i][j][2]), "+f"(acc[i][j][3])
                        : "r"(af[i][0]), "r"(af[i][1]), "r"(af[i][2]), "r"(af[i][3]),
                          "r"(bf[j][0]), "r"(bf[j][1]));
                }
        }
        __syncthreads();
        if (it+1 < NIT){
            sts_tile();
            __syncthreads();
        }
    }
    #pragma unroll
    for (int i=0;i<MT;i++){
        int r0 = bm0 + wm*WM + i*16 + gid;
        #pragma unroll
        for (int j=0;j<NT;j++){
            int cc = bn0 + wn*WN + j*8 + qid*2;
            float b0 = BIAS ? bias[cc] : 0.f;
            float b1 = BIAS ? bias[cc+1] : 0.f;
            float2 v0, v1;
            v0.x = alpha*acc[i][j][0] + b0;
            v0.y = alpha*acc[i][j][1] + b1;
            v1.x = alpha*acc[i][j][2] + b0;
            v1.y = alpha*acc[i][j][3] + b1;
            *(float2*)(C + (size_t) r0   *N + cc) = v0;
            *(float2*)(C + (size_t)(r0+8)*N + cc) = v1;
        }
    }
}

#define HID_SMEM ((64*36 + 32*72)*4)
__global__ void __launch_bounds__(256) mma_hid_kernel(const float* __restrict__ Bw,
                                                      const float* __restrict__ bias){
    extern __shared__ unsigned dyn[];
    unsigned* As = dyn;
    unsigned* Bs = dyn + 64*36;
    mma_body<64,64,32,16,32,true>(g_acc, Bw, g_nf, HID, DIMF,
                                  0.2f, bias, As, Bs);
}

// ---------------- launch 5 (per layer): LN + leaky + feat/acc update + next su ----------------
__global__ void ln_su_kernel(const float* __restrict__ linb,
                             const float* __restrict__ lng,
                             const float* __restrict__ lnb,
                             const float* __restrict__ a1next){
    int n = blockIdx.x, tid = threadIdx.x;
    float4 x = ((const float4*)g_gemm)[(size_t)n*256+tid];
    float4 bb = ((const float4*)linb)[tid];
    x.x+=bb.x; x.y+=bb.y; x.z+=bb.z; x.w+=bb.w;
    __shared__ float sm[32];
    float s = x.x+x.y+x.z+x.w;
    s = block_reduce_256(s, sm);
    float mu = s*(1.f/1024.f);
    float d0=x.x-mu, d1=x.y-mu, d2=x.z-mu, d3=x.w-mu;
    float q = d0*d0+d1*d1+d2*d2+d3*d3;
    q = block_reduce_256(q, sm);
    float r = rsqrtf(q*(1.f/1024.f)+EPSV);
    float4 gg = ((const float4*)lng)[tid];
    float4 b2 = ((const float4*)lnb)[tid];
    float4 y;
    y.x = lk(gg.x*d0*r + b2.x);
    y.y = lk(gg.y*d1*r + b2.y);
    y.z = lk(gg.z*d2*r + b2.z);
    y.w = lk(gg.w*d3*r + b2.w);
    ((float4*)g_feat)[(size_t)n*256+tid] = y;
    float4 a = ((float4*)g_acc)[(size_t)n*256+tid];
    a.x+=y.x; a.y+=y.y; a.z+=y.z; a.w+=y.w;
    ((float4*)g_acc)[(size_t)n*256+tid] = a;
    if (a1next){
        float4 av = ((const float4*)a1next)[tid];
        float p = y.x*av.x + y.y*av.y + y.z*av.z + y.w*av.w;
        p = block_reduce_256(p, sm);
        if (tid==0) g_su[n]=p;
    }
}

// ---------------- zeroing (surface/ns branch only) ----------------
__global__ void zero_kernel(){
    int i = blockIdx.x*256 + threadIdx.x;
    if (i < NNODES*HID) g_ressum[i] = 0.f;
    if (i < NNODES) g_rescnt[i]=0.f;
    if (i < 2*HID){ g_stats[i]=0.f; g_stats2[i]=0.f; }
    if (i < NGRAPH*HID) g_nssum[i]=0.f;
    if (i < NGRAPH) g_nscnt[i]=0.f;
}

// ---------------- surface path ----------------
__global__ void surf_lin_kernel(const float* __restrict__ sf,
                                const float* __restrict__ W,
                                const float* __restrict__ b){
    int c  = threadIdx.x & 63;
    int ry = threadIdx.x >> 6;
    int row0 = blockIdx.x * 64;
    float w0=W[c], w1=W[64+c], w2=W[128+c], bc=b[c];
    float ls=0.f, lss=0.f;
    for (int r=ry; r<64; r+=4){
        int row = row0 + r;
        float x0=sf[row*3], x1=sf[row*3+1], x2=sf[row*3+2];
        float y = fmaf(x0,w0, fmaf(x1,w1, fmaf(x2,w2, bc)));
        g_surfy[row*64+c]=y; ls+=y; lss+=y*y;
    }
    __shared__ float ss[256], sq[256];
    ss[threadIdx.x]=ls; sq[threadIdx.x]=lss;
    __syncthreads();
    if (ry==0){
        float t  = ss[c]+ss[64+c]+ss[128+c]+ss[192+c];
        float t2 = sq[c]+sq[64+c]+sq[128+c]+sq[192+c];
        atomicAdd(&g_stats[c], t);
        atomicAdd(&g_stats[64+c], t2);
    }
}

__global__ void finalize_stats_kernel(int which, float n){
    float* st = which ? g_stats2 : g_stats;
    int c = threadIdx.x;
    float mu  = st[c] / n;
    float var = st[64+c]/n - mu*mu;
    st[c]   = mu;
    st[64+c]= rsqrtf(fmaxf(var,0.f)+EPSV);
}

__global__ void surf_norm_scatter_kernel(const int* __restrict__ surf_res,
                                         const float* __restrict__ g,
                                         const float* __restrict__ beta){
    int idx = blockIdx.x*256 + threadIdx.x;
    int row = idx >> 6, c = idx & 63;
    float y = g_surfy[idx];
    float v = lk(g[c]*(y - g_stats[c])*g_stats[64+c] + beta[c]);
    int t = surf_res[row];
    atomicAdd(&g_ressum[t*64 + c], v);
    if (c==0) atomicAdd(&g_rescnt[t], 1.f);
}

__global__ void gather_s_kernel(const int* __restrict__ uniq){
    int idx = blockIdx.x*256 + threadIdx.x;
    int i = idx >> 6, c = idx & 63;
    int u = uniq[i];
    g_s[idx] = g_ressum[u*64+c] / fmaxf(g_rescnt[u], 1.f);
}

// ---------------- final heads ----------------
__global__ void prot_kernel(const float* __restrict__ g,
                            const float* __restrict__ b,
                            float* __restrict__ out){
    int gr = blockIdx.x, c = threadIdx.x;
    const float* base = g_nf + (size_t)gr*512*64;
    float s = 0.f;
    for (int r=0;r<512;r++) s += base[r*64+c];
    float x = s*(1.f/512.f);
    __shared__ float sm[64];
    __shared__ float s_mu, s_r;
    sm[c]=x; __syncthreads();
    if (c==0){ float t=0.f; for (int i=0;i<64;i++) t+=sm[i]; s_mu=t*(1.f/64.f); }
    __syncthreads();
    float d = x - s_mu;
    sm[c]=d*d; __syncthreads();
    if (c==0){ float t=0.f; for (int i=0;i<64;i++) t+=sm[i]; s_r=rsqrtf(t*(1.f/64.f)+EPSV); }
    __syncthreads();
    out[gr*64+c] = lk(g[c]*d*s_r + b[c]);
}

__global__ void ns_a_kernel(const int* __restrict__ uniq,
                            const float* __restrict__ dw,
                            const float* __restrict__ db){
    __shared__ float s_wd[128*64];
    __shared__ float z_s[128];
    int tid = threadIdx.x;
    for (int i=tid; i<128*64; i+=64) s_wd[i]=dw[i];
    float bc = db[tid];
    float ls=0.f, lss=0.f;
    __syncthreads();
    int row0 = blockIdx.x*64;
    for (int r=0;r<64;r++){
        int row = row0 + r;
        if (row >= NUNIQ) break;
        z_s[tid]      = g_nf[(size_t)uniq[row]*64 + tid];
        z_s[64+tid]   = g_s[(size_t)row*64 + tid];
        __syncthreads();
        float y = bc;
        #pragma unroll 8
        for (int k=0;k<128;k++) y = fmaf(z_s[k], s_wd[k*64+tid], y);
        g_y2[(size_t)row*64+tid] = y;
        ls += y; lss += y*y;
        __syncthreads();
    }
    atomicAdd(&g_stats2[tid], ls);
    atomicAdd(&g_stats2[64+tid], lss);
}

__global__ void ns_norm_scatter_kernel(const int* __restrict__ res_batch,
                                       const float* __restrict__ g,
                                       const float* __restrict__ beta){
    int idx = blockIdx.x*256 + threadIdx.x;
    int row = idx >> 6, c = idx & 63;
    float y = g_y2[idx];
    float v = lk(g[c]*(y - g_stats2[c])*g_stats2[64+c] + beta[c]);
    int t = res_batch[row];
    atomicAdd(&g_nssum[t*64 + c], v);
    if (c==0) atomicAdd(&g_nscnt[t], 1.f);
}

__global__ void ns_final_kernel(const float* __restrict__ bng,
                                const float* __restrict__ bnb,
                                float* __restrict__ out){
    int tid = threadIdx.x;
    int gr = tid >> 6, c = tid & 63;
    float v = g_nssum[tid] / fmaxf(g_nscnt[gr], 1.f);
    __shared__ float sm[1024];
    __shared__ float s_mu[64], s_r[64];
    sm[tid]=v; __syncthreads();
    if (gr==0){
        float t=0.f, t2=0.f;
        for (int r=0;r<16;r++){ float x=sm[r*64+c]; t+=x; t2+=x*x; }
        float mu = t*(1.f/16.f);
        s_mu[c]=mu;
        s_r[c]=rsqrtf(fmaxf(t2*(1.f/16.f)-mu*mu,0.f)+EPSV);
    }
    __syncthreads();
    out[16*64 + tid] = lk(bng[c]*(v - s_mu[c])*s_r[c] + bnb[c]);
}

// ---------------- host ----------------
extern "C" void kernel_launch(void* const* d_in, const int* in_sizes, int n_in,
                              void* d_out, int out_size){
    const int*   ei         = (const int*)  d_in[0];
    const float* n_feats    = (const float*)d_in[1];
    const float* surf_feats = (const float*)d_in[3];
    const int*   surf_res   = (const int*)  d_in[4];
    const int*   res_batch  = (const int*)  d_in[5];
    const int*   uniq       = (const int*)  d_in[6];
    const float* surf_up_w  = (const float*)d_in[7];
    const float* surf_up_b  = (const float*)d_in[8];
    const float* surf_up_g  = (const float*)d_in[9];
    const float* surf_up_be = (const float*)d_in[10];
    const float* a_w        = (const float*)d_in[11];
    const float* lin_w      = (const float*)d_in[12];
    const float* lin_b      = (const float*)d_in[13];
    const float* ln_g       = (const float*)d_in[14];
    const float* ln_b       = (const float*)d_in[15];
    const float* hid_w      = (const float*)d_in[16];
    const float* hid_b      = (const float*)d_in[17];
    const float* down_w     = (const float*)d_in[18];
    const float* down_b     = (const float*)d_in[19];
    const float* down_g     = (const float*)d_in[20];
    const float* down_be    = (const float*)d_in[21];
    const float* prot_ln_g  = (const float*)d_in[22];
    const float* prot_ln_b  = (const float*)d_in[23];
    const float* surf_bn_g  = (const float*)d_in[24];
    const float* surf_bn_b  = (const float*)d_in[25];
    float* out = (float*)d_out;

    cudaFuncSetAttribute(mma_main_kernel,
                         cudaFuncAttributeMaxDynamicSharedMemorySize, MAIN_SMEM);
    cudaFuncSetAttribute(mma_hid_kernel,
                         cudaFuncAttributeMaxDynamicSharedMemorySize, HID_SMEM);

    degfill_kernel<<<1, 1024>>>(ei);                                // 1
    init_su_kernel<<<NNODES, 256>>>(n_feats, a_w, lin_w);           // 2

    for (int l=0; l<4; l++){
        smagg_kernel<<<NNODES, 256>>>();                            // 3
        mma_main_kernel<<<dim3(DIMF/128, NNODES/128), 256, MAIN_SMEM>>>(l); // 4 <- profiled
        const float* a1n = (l<3) ? (a_w + (size_t)(l+1)*2*DIMF) : nullptr;
        ln_su_kernel<<<NNODES, 256>>>(lin_b + (size_t)l*DIMF,       // 5
                                      ln_g + (size_t)l*DIMF,
                                      ln_b + (size_t)l*DIMF, a1n);
    }

    mma_hid_kernel<<<dim3(1, NNODES/64), 256, HID_SMEM>>>(hid_w, hid_b);
    prot_kernel<<<NGRAPH, 64>>>(prot_ln_g, prot_ln_b, out);

    zero_kernel<<<(NNODES*HID)/256, 256>>>();
    surf_lin_kernel<<<NSURF/64, 256>>>(surf_feats, surf_up_w, surf_up_b);
    finalize_stats_kernel<<<1,64>>>(0, (float)NSURF);
    surf_norm_scatter_kernel<<<(NSURF*HID)/256, 256>>>(surf_res, surf_up_g, surf_up_be);
    gather_s_kernel<<<(NUNIQ*HID)/256, 256>>>(uniq);

    ns_a_kernel<<<(NUNIQ+63)/64, 64>>>(uniq, down_w, down_b);
    finalize_stats_kernel<<<1,64>>>(1, (float)NUNIQ);
    ns_norm_scatter_kernel<<<(NUNIQ*HID)/256, 256>>>(res_batch, down_g, down_be);
    ns_final_kernel<<<1,1024>>>(surf_bn_g, surf_bn_b, out);
}